// round 2
// baseline (speedup 1.0000x reference)
#include <cuda_runtime.h>
#include <cuda_bf16.h>
#include <cstdint>

typedef __nv_bfloat16 bf16;

#define Bx 4
#define Sx 2048
#define Hx 1024
#define Mx 8192            // B*S
#define CH 128             // scan chunk length
#define NCH 16             // S / CH

// ---------------- device scratch (allocation-free rule: __device__ globals) ----
__device__ __align__(256) bf16  g_Xhi[Mx * Hx];
__device__ __align__(256) bf16  g_Xlo[Mx * Hx];
__device__ __align__(256) bf16  g_Whi[3 * Hx * Hx];   // [Wi, Wf, Wg]
__device__ __align__(256) bf16  g_Wlo[3 * Hx * Hx];
__device__ __align__(256) bf16  g_Wohi[Hx * Hx];
__device__ __align__(256) bf16  g_Wolo[Hx * Hx];
__device__ __align__(256) float g_Yi[Mx * Hx];        // i_raw -> inp (in place)
__device__ __align__(256) float g_Yf[Mx * Hx];        // f_raw -> f -> cumprod (in place)
__device__ __align__(256) float g_Yg[Mx * Hx];        // g (raw)
__device__ __align__(256) bf16  g_GHhi[Mx * Hx];
__device__ __align__(256) bf16  g_GHlo[Mx * Hx];
__device__ float g_P[Bx * NCH * Hx];
__device__ float g_E[Bx * NCH * Hx];
__device__ float g_Cr[Bx * NCH * Hx];

// ---------------- PTX helpers ----------------
__device__ __forceinline__ uint32_t smem_u32(const void* p) {
    uint32_t a;
    asm("{ .reg .u64 t; cvta.to.shared.u64 t, %1; cvt.u32.u64 %0, t; }" : "=r"(a) : "l"(p));
    return a;
}

__device__ __forceinline__ void ldsm_x4(uint32_t& r0, uint32_t& r1, uint32_t& r2,
                                        uint32_t& r3, uint32_t addr) {
    asm volatile("ldmatrix.sync.aligned.m8n8.x4.shared.b16 {%0,%1,%2,%3}, [%4];"
                 : "=r"(r0), "=r"(r1), "=r"(r2), "=r"(r3) : "r"(addr));
}

__device__ __forceinline__ void mma_bf16(float* c, const uint32_t* a, const uint32_t* b) {
    asm volatile(
        "mma.sync.aligned.m16n8k16.row.col.f32.bf16.bf16.f32 "
        "{%0,%1,%2,%3}, {%4,%5,%6,%7}, {%8,%9}, {%0,%1,%2,%3};"
        : "+f"(c[0]), "+f"(c[1]), "+f"(c[2]), "+f"(c[3])
        : "r"(a[0]), "r"(a[1]), "r"(a[2]), "r"(a[3]), "r"(b[0]), "r"(b[1]));
}

// ---------------- GEMM: C[M,N] = A[M,K] @ W[N,K]^T, bf16x3-split, fp32 out ---
// CTA tile 128x128, K-chunk 64, 3-stage cp.async pipeline, 8 warps (2x4),
// warp tile 64x32, mma.sync m16n8k16 bf16 with fp32 accumulators.
#define STAGE_BYTES 65536u          // 4 tiles x (128 x 64 bf16) = 4 x 16KB
#define GEMM_SMEM   (1024 + 3 * 65536)

__device__ __forceinline__ void load_tile(uint32_t tb, const bf16* __restrict__ src,
                                          int row0, int k0, int tid) {
    const char* gbase = (const char*)(src + (size_t)row0 * Hx + k0);
#pragma unroll
    for (int i = 0; i < 4; i++) {
        int gid = tid + i * 256;        // 1024 granules of 16B
        int row = gid >> 3;
        int g   = gid & 7;
        const char* gp = gbase + (size_t)row * (Hx * 2) + g * 16;
        uint32_t sp = tb + (uint32_t)(row * 128) + (uint32_t)((g ^ (row & 7)) << 4);
        asm volatile("cp.async.cg.shared.global [%0], [%1], 16;"
                     :: "r"(sp), "l"(gp) : "memory");
    }
}

__global__ void __launch_bounds__(256, 1) k_gemm(
    const bf16* __restrict__ Ah, const bf16* __restrict__ Al,
    const bf16* __restrict__ Bh_, const bf16* __restrict__ Bl_,
    float* __restrict__ C0, float* __restrict__ C1, float* __restrict__ C2,
    int zstride)
{
    extern __shared__ char smem_raw[];
    uint32_t sb     = smem_u32(smem_raw);
    uint32_t stage0 = (sb + 1023u) & ~1023u;

    const int tid = threadIdx.x;
    const int wid = tid >> 5;
    const int lid = tid & 31;
    const int wr  = wid >> 2;       // 0-1  -> m offset wr*64
    const int wc  = wid & 3;        // 0-3  -> n offset wc*32
    const int n0  = blockIdx.x * 128;
    const int m0  = blockIdx.y * 128;
    const int z   = blockIdx.z;
    const bf16* Bh = Bh_ + (size_t)z * zstride;
    const bf16* Bl = Bl_ + (size_t)z * zstride;
    float* C = (z == 0) ? C0 : ((z == 1) ? C1 : C2);

    // prologue: fill 3 stages
#pragma unroll
    for (int s = 0; s < 3; s++) {
        uint32_t st = stage0 + s * STAGE_BYTES;
        load_tile(st,          Ah, m0, s * 64, tid);
        load_tile(st + 16384u, Al, m0, s * 64, tid);
        load_tile(st + 32768u, Bh, n0, s * 64, tid);
        load_tile(st + 49152u, Bl, n0, s * 64, tid);
        asm volatile("cp.async.commit_group;" ::: "memory");
    }

    float acc[4][4][4];
#pragma unroll
    for (int a = 0; a < 4; a++)
#pragma unroll
        for (int b = 0; b < 4; b++)
#pragma unroll
            for (int c = 0; c < 4; c++) acc[a][b][c] = 0.f;

    // ldmatrix address components (within a 128-row x 64-col bf16 tile,
    // 128B/row, 8 16B colgroups, XOR-swizzled)
    const int aRow = lid & 15;                       // + wr*64 + mt*16
    const int aCg  = lid >> 4;                       // + 2*ks
    const int bRow = (lid & 7) | ((lid & 16) >> 1);  // + wc*32 + nt*16
    const int bCg  = (lid >> 3) & 1;                 // + 2*ks

    for (int k = 0; k < 16; k++) {
        int st = k % 3;
        uint32_t sbase = stage0 + st * STAGE_BYTES;

        if (k <= 13)      asm volatile("cp.async.wait_group 2;" ::: "memory");
        else if (k == 14) asm volatile("cp.async.wait_group 1;" ::: "memory");
        else              asm volatile("cp.async.wait_group 0;" ::: "memory");
        __syncthreads();

#pragma unroll
        for (int ks = 0; ks < 4; ks++) {
            uint32_t ah[4][4], al[4][4], bhf[2][4], blf[2][4];
            // A fragments (hi, lo): 4 m16 tiles
#pragma unroll
            for (int mt = 0; mt < 4; mt++) {
                int r  = wr * 64 + mt * 16 + aRow;
                int cg = 2 * ks + aCg;
                uint32_t off = (uint32_t)(r * 128) + (uint32_t)((cg ^ (r & 7)) << 4);
                ldsm_x4(ah[mt][0], ah[mt][1], ah[mt][2], ah[mt][3], sbase + off);
                ldsm_x4(al[mt][0], al[mt][1], al[mt][2], al[mt][3], sbase + 16384u + off);
            }
            // B fragments (hi, lo): 2 n16 tiles (each = two n8 frags)
#pragma unroll
            for (int nt = 0; nt < 2; nt++) {
                int r  = wc * 32 + nt * 16 + bRow;
                int cg = 2 * ks + bCg;
                uint32_t off = (uint32_t)(r * 128) + (uint32_t)((cg ^ (r & 7)) << 4);
                ldsm_x4(bhf[nt][0], bhf[nt][1], bhf[nt][2], bhf[nt][3], sbase + 32768u + off);
                ldsm_x4(blf[nt][0], blf[nt][1], blf[nt][2], blf[nt][3], sbase + 49152u + off);
            }
            // 3 split terms: Ah*Bh + Ah*Bl + Al*Bh
#pragma unroll
            for (int mt = 0; mt < 4; mt++)
#pragma unroll
                for (int nt = 0; nt < 4; nt++) {
                    const uint32_t* bh2 = &bhf[nt >> 1][(nt & 1) * 2];
                    const uint32_t* bl2 = &blf[nt >> 1][(nt & 1) * 2];
                    mma_bf16(acc[mt][nt], ah[mt], bh2);
                    mma_bf16(acc[mt][nt], ah[mt], bl2);
                    mma_bf16(acc[mt][nt], al[mt], bh2);
                }
        }

        __syncthreads();   // all warps done reading stage st

        int kn = k + 3;
        if (kn < 16) {
            load_tile(sbase,          Ah, m0, kn * 64, tid);
            load_tile(sbase + 16384u, Al, m0, kn * 64, tid);
            load_tile(sbase + 32768u, Bh, n0, kn * 64, tid);
            load_tile(sbase + 49152u, Bl, n0, kn * 64, tid);
            asm volatile("cp.async.commit_group;" ::: "memory");
        }
    }

    // epilogue: fp32 accumulators straight to gmem
    const int g4 = lid >> 2;        // 0-7
    const int t4 = lid & 3;         // 0-3
#pragma unroll
    for (int mt = 0; mt < 4; mt++) {
        int row = m0 + wr * 64 + mt * 16 + g4;
#pragma unroll
        for (int nt = 0; nt < 4; nt++) {
            int col = n0 + wc * 32 + nt * 8 + t4 * 2;
            float2 v0 = make_float2(acc[mt][nt][0], acc[mt][nt][1]);
            float2 v1 = make_float2(acc[mt][nt][2], acc[mt][nt][3]);
            *(float2*)(C + (size_t)row * Hx + col)       = v0;
            *(float2*)(C + (size_t)(row + 8) * Hx + col) = v1;
        }
    }
}

// ---------------- small kernels ----------------
__global__ void k_split(const float* __restrict__ src, bf16* __restrict__ hi,
                        bf16* __restrict__ lo, int n) {
    int i = blockIdx.x * blockDim.x + threadIdx.x;
    if (i < n) {
        float x = src[i];
        bf16 h = __float2bfloat16(x);
        hi[i] = h;
        lo[i] = __float2bfloat16(x - __bfloat162float(h));
    }
}

__global__ void k_act(int n) {
    int i = blockIdx.x * blockDim.x + threadIdx.x;
    if (i < n) {
        float yf = g_Yf[i], yi = g_Yi[i];
        float f = 1.f / (1.f + expf(-yf));
        float s = 1.f / (1.f + expf(-yi));
        g_Yf[i] = f;
        g_Yi[i] = yi * s * (1.f - f);     // SiLU(i) * (1 - f)
    }
}

// pass 1: chunk-local scan; overwrite Yf with cumprod(f), Yi with local h
__global__ void k_scan1() {
    int tid = blockIdx.x * blockDim.x + threadIdx.x;   // B*NCH*H = 65536
    int h  = tid & (Hx - 1);
    int bc = tid >> 10;          // b*NCH + c
    int b  = bc >> 4;
    int c  = bc & (NCH - 1);
    size_t base = ((size_t)(b * Sx + c * CH)) * Hx + h;
    float p = 1.f, hl = 0.f;
#pragma unroll 4
    for (int t = 0; t < CH; t++) {
        size_t idx = base + (size_t)t * Hx;
        float f  = g_Yf[idx];
        float in = g_Yi[idx];
        hl = f * hl + in;
        p  = p * f;
        g_Yf[idx] = p;
        g_Yi[idx] = hl;
    }
    g_P[tid] = p;
    g_E[tid] = hl;
}

// pass 2: scan across chunks per channel
__global__ void k_scan2() {
    int tid = blockIdx.x * blockDim.x + threadIdx.x;   // B*H = 4096
    int h = tid & (Hx - 1);
    int b = tid >> 10;
    float carry = 0.f;
#pragma unroll
    for (int c = 0; c < NCH; c++) {
        int idx = ((b * NCH + c) << 10) + h;
        g_Cr[idx] = carry;
        carry = g_P[idx] * carry + g_E[idx];
    }
}

// pass 3: h = h_local + cumprod(f)*carry; gh = g*h; write bf16 hi/lo split
__global__ void k_scan3(int n) {
    int i = blockIdx.x * blockDim.x + threadIdx.x;
    if (i < n) {
        int h = i & (Hx - 1);
        int s = (i >> 10) & (Sx - 1);
        int b = i >> 21;
        int c = s >> 7;
        float carry = g_Cr[((b * NCH + c) << 10) + h];
        float hv = g_Yi[i] + g_Yf[i] * carry;
        float gh = g_Yg[i] * hv;
        bf16 hi = __float2bfloat16(gh);
        g_GHhi[i] = hi;
        g_GHlo[i] = __float2bfloat16(gh - __bfloat162float(hi));
    }
}

// ---------------- launch ----------------
extern "C" void kernel_launch(void* const* d_in, const int* in_sizes, int n_in,
                              void* d_out, int out_size) {
    const float* x  = (const float*)d_in[0];
    const float* Wi = (const float*)d_in[1];
    const float* Wf = (const float*)d_in[2];
    const float* Wg = (const float*)d_in[3];
    const float* Wo = (const float*)d_in[4];
    float* out = (float*)d_out;

    cudaFuncSetAttribute(k_gemm, cudaFuncAttributeMaxDynamicSharedMemorySize, GEMM_SMEM);

    bf16 *Xhi, *Xlo, *Whi, *Wlo, *Wohi, *Wolo, *GHhi, *GHlo;
    float *Yi, *Yf, *Yg;
    cudaGetSymbolAddress((void**)&Xhi,  g_Xhi);
    cudaGetSymbolAddress((void**)&Xlo,  g_Xlo);
    cudaGetSymbolAddress((void**)&Whi,  g_Whi);
    cudaGetSymbolAddress((void**)&Wlo,  g_Wlo);
    cudaGetSymbolAddress((void**)&Wohi, g_Wohi);
    cudaGetSymbolAddress((void**)&Wolo, g_Wolo);
    cudaGetSymbolAddress((void**)&GHhi, g_GHhi);
    cudaGetSymbolAddress((void**)&GHlo, g_GHlo);
    cudaGetSymbolAddress((void**)&Yi,   g_Yi);
    cudaGetSymbolAddress((void**)&Yf,   g_Yf);
    cudaGetSymbolAddress((void**)&Yg,   g_Yg);

    const int NE = Mx * Hx;     // 8388608
    const int NW = Hx * Hx;     // 1048576

    // bf16 hi/lo splits
    k_split<<<NE / 256, 256>>>(x,  Xhi,          Xlo,          NE);
    k_split<<<NW / 256, 256>>>(Wi, Whi,          Wlo,          NW);
    k_split<<<NW / 256, 256>>>(Wf, Whi + NW,     Wlo + NW,     NW);
    k_split<<<NW / 256, 256>>>(Wg, Whi + 2 * NW, Wlo + 2 * NW, NW);
    k_split<<<NW / 256, 256>>>(Wo, Wohi,         Wolo,         NW);

    // GEMM1: Yi = x@Wi^T, Yf = x@Wf^T, Yg = x@Wg^T (z-fused)
    dim3 g1(Hx / 128, Mx / 128, 3);
    k_gemm<<<g1, 256, GEMM_SMEM>>>(Xhi, Xlo, Whi, Wlo, Yi, Yf, Yg, NW);

    // gates
    k_act<<<NE / 256, 256>>>(NE);

    // chunked linear recurrence
    k_scan1<<<(Bx * NCH * Hx) / 256, 256>>>();
    k_scan2<<<(Bx * Hx) / 256, 256>>>();
    k_scan3<<<NE / 256, 256>>>(NE);

    // GEMM2: out = (g*h) @ Wo^T
    dim3 g2(Hx / 128, Mx / 128, 1);
    k_gemm<<<g2, 256, GEMM_SMEM>>>(GHhi, GHlo, Wohi, Wolo, out, out, out, 0);
}